// round 1
// baseline (speedup 1.0000x reference)
#include <cuda_runtime.h>
#include <cstdint>
#include <math.h>

// ---------------- problem constants ----------------
#define NB   16
#define SL   4096
#define DM   64          // d_model
#define DIN  128         // d_inner
#define DST  32          // d_state
#define NH   2           // heads
#define HD   64          // headdim
#define CDIM 192         // d_inner + 2*d_state
#define NPJ  322         // 2*128 + 2*32 + 2
#define ZST  324         // padded row stride for zxbcdt (16B-aligned rows)
#define MROWS (NB*SL)    // 65536

// ---------------- device scratch (no runtime allocation allowed) ----------------
__device__ float  g_zx [(size_t)MROWS * ZST];   // zxbcdt, padded stride 324
__device__ float  g_xbc[(size_t)MROWS * CDIM];  // conv+silu activated xBC
__device__ float2 g_dtA[(size_t)MROWS * 2];     // {dt, exp(dt*A)} per (row, head)
__device__ float  g_y  [(size_t)MROWS * DIN];   // scan output
__device__ float  g_buf[2][(size_t)MROWS * DM]; // layer ping-pong

// ---------------- K1: in-projection GEMM (M=65536, N=322, K=64) ----------------
// Block tile 128x64, 256 threads, micro-tile 8x4, K=64 single-shot in shared.
__global__ __launch_bounds__(256) void k_inproj(const float* __restrict__ xin, int insel,
                                                const float* __restrict__ W) {
    __shared__ float As[128][64];   // row-major, straight copy (K==64 == row width)
    __shared__ float Bs[64][64];
    const float* in = (insel >= 0) ? g_buf[insel] : xin;
    const int m0 = blockIdx.y * 128;
    const int n0 = blockIdx.x * 64;
    const int tid = threadIdx.x;

    // A tile: 128 rows x 64 k -> contiguous 8192 floats
    const float4* A4 = (const float4*)(in + (size_t)m0 * DM);
    float4* As4 = (float4*)&As[0][0];
#pragma unroll
    for (int i = 0; i < 8; i++) As4[i * 256 + tid] = A4[i * 256 + tid];

    // B tile: Win rows k in [0,64), cols n0..n0+63 (stride 322), predicated
#pragma unroll
    for (int i = 0; i < 16; i++) {
        int idx = i * 256 + tid;
        int k = idx >> 6, n = idx & 63;
        int gn = n0 + n;
        Bs[k][n] = (gn < NPJ) ? W[k * NPJ + gn] : 0.f;
    }
    __syncthreads();

    const int tx = tid & 15, ty = tid >> 4;
    float acc[8][4];
#pragma unroll
    for (int i = 0; i < 8; i++)
#pragma unroll
        for (int j = 0; j < 4; j++) acc[i][j] = 0.f;

#pragma unroll
    for (int k4 = 0; k4 < 16; k4++) {
        float4 b0 = *(const float4*)&Bs[k4 * 4 + 0][tx * 4];
        float4 b1 = *(const float4*)&Bs[k4 * 4 + 1][tx * 4];
        float4 b2 = *(const float4*)&Bs[k4 * 4 + 2][tx * 4];
        float4 b3 = *(const float4*)&Bs[k4 * 4 + 3][tx * 4];
#pragma unroll
        for (int i = 0; i < 8; i++) {
            float4 a = *(const float4*)&As[ty * 8 + i][k4 * 4];
            acc[i][0] += a.x * b0.x + a.y * b1.x + a.z * b2.x + a.w * b3.x;
            acc[i][1] += a.x * b0.y + a.y * b1.y + a.z * b2.y + a.w * b3.y;
            acc[i][2] += a.x * b0.z + a.y * b1.z + a.z * b2.z + a.w * b3.z;
            acc[i][3] += a.x * b0.w + a.y * b1.w + a.z * b2.w + a.w * b3.w;
        }
    }

    if (n0 + 64 <= NPJ) {
#pragma unroll
        for (int i = 0; i < 8; i++) {
            size_t r = (size_t)(m0 + ty * 8 + i) * ZST + n0 + tx * 4;
            *(float4*)&g_zx[r] = make_float4(acc[i][0], acc[i][1], acc[i][2], acc[i][3]);
        }
    } else {  // n0 == 320, only cols 320,321 valid
#pragma unroll
        for (int i = 0; i < 8; i++)
#pragma unroll
            for (int j = 0; j < 4; j++) {
                int gn = n0 + tx * 4 + j;
                if (gn < NPJ) g_zx[(size_t)(m0 + ty * 8 + i) * ZST + gn] = acc[i][j];
            }
    }
}

// ---------------- K1b: dt = softplus(raw + bias), dA = exp(dt * A) ----------------
__global__ __launch_bounds__(256) void k_dt(const float* __restrict__ dt_bias,
                                            const float* __restrict__ A_log) {
    int i = blockIdx.x * 256 + threadIdx.x;     // over 65536*2
    if (i >= MROWS * 2) return;
    int row = i >> 1, hh = i & 1;
    float v = g_zx[(size_t)row * ZST + 320 + hh] + dt_bias[hh];
    float dt = (v > 15.f) ? v : log1pf(expf(v));
    float A = -expf(A_log[hh]);
    g_dtA[i] = make_float2(dt, expf(dt * A));
}

// ---------------- K2: depthwise causal conv(4) + bias + SiLU ----------------
// Block: 192 threads (one per channel) x 32 timesteps. Grid: (SL/32, NB).
__global__ __launch_bounds__(192) void k_conv(const float* __restrict__ cw,
                                              const float* __restrict__ cb) {
    __shared__ float s[35][192];
    const int b = blockIdx.y, t0 = blockIdx.x * 32, c = threadIdx.x;
    const float* base = g_zx + (size_t)b * SL * ZST + 128 + c;
#pragma unroll
    for (int r = 0; r < 35; r++) {
        int t = t0 - 3 + r;
        s[r][c] = (t >= 0) ? base[(size_t)t * ZST] : 0.f;
    }
    __syncthreads();
    const float w0 = cw[c * 4 + 0], w1 = cw[c * 4 + 1];
    const float w2 = cw[c * 4 + 2], w3 = cw[c * 4 + 3];
    const float bb = cb[c];
    float* ob = g_xbc + ((size_t)b * SL + t0) * CDIM + c;
#pragma unroll
    for (int tt = 0; tt < 32; tt++) {
        float v = bb + w0 * s[tt][c] + w1 * s[tt + 1][c] + w2 * s[tt + 2][c] + w3 * s[tt + 3][c];
        v = v / (1.f + expf(-v));   // silu
        ob[(size_t)tt * CDIM] = v;
    }
}

// ---------------- K3: selective scan ----------------
// One warp per (b, h, p): 32-dim state in registers (one n per lane).
// No block syncs — the recurrence is independent per output row.
__global__ __launch_bounds__(128) void k_scan(const float* __restrict__ Dp) {
    const int wg = blockIdx.x * 4 + (threadIdx.x >> 5);
    const int lane = threadIdx.x & 31;
    const int b = wg >> 7;           // 128 warps per batch (2 heads * 64 p)
    const int rem = wg & 127;
    const int h = rem >> 6;
    const int p = rem & 63;

    const float* pB = g_xbc + (size_t)b * SL * CDIM + 128 + lane;
    const float* pC = pB + 32;
    const float* pX = g_xbc + (size_t)b * SL * CDIM + h * 64 + p;
    const float2* pD = g_dtA + (size_t)b * SL * 2 + h;
    float* pY = g_y + (size_t)b * SL * DIN + h * 64 + p;
    const float dp = Dp[h];

    float hs = 0.f;
#pragma unroll 4
    for (int t = 0; t < SL; t++) {
        float Bv = pB[0];
        float Cv = pC[0];
        float xv = pX[0];
        float2 da = pD[0];
        hs = da.y * hs + (da.x * xv) * Bv;
        float part = hs * Cv;
        part += __shfl_xor_sync(0xffffffffu, part, 16);
        part += __shfl_xor_sync(0xffffffffu, part, 8);
        part += __shfl_xor_sync(0xffffffffu, part, 4);
        part += __shfl_xor_sync(0xffffffffu, part, 2);
        part += __shfl_xor_sync(0xffffffffu, part, 1);
        if (lane == 0) pY[0] = part + dp * xv;
        pB += CDIM; pC += CDIM; pX += CDIM; pD += 2; pY += DIN;
    }
}

// ---------------- K4: gate*silu(z) -> RMSNorm -> out-proj GEMM (K=128, N=64) ----------------
// Block tile 32 rows, 256 threads; Gs (normalized activations) + Wout in shared.
__global__ __launch_bounds__(256) void k_out(const float* __restrict__ nw,
                                             const float* __restrict__ Wout,
                                             float* __restrict__ dout, int outsel) {
    __shared__ float Gs[32][128];
    __shared__ float Ws[128][64];
    float* out = (outsel >= 0) ? g_buf[outsel] : dout;
    const int m0 = blockIdx.x * 32;
    const int tid = threadIdx.x;

    // Wout tile: 128x64 contiguous
    float4* Ws4 = (float4*)&Ws[0][0];
    const float4* W4 = (const float4*)Wout;
#pragma unroll
    for (int i = 0; i < 8; i++) Ws4[i * 256 + tid] = W4[i * 256 + tid];

    // phase 1: row m = tid/8, 16 cols per thread
    const int m = tid >> 3, l8 = tid & 7;
    const float* yrow = g_y + (size_t)(m0 + m) * DIN + l8 * 16;
    const float* zrow = g_zx + (size_t)(m0 + m) * ZST + l8 * 16;
    float4 gv[4];
    float ss = 0.f;
#pragma unroll
    for (int q = 0; q < 4; q++) {
        float4 yv = *(const float4*)(yrow + q * 4);
        float4 zv = *(const float4*)(zrow + q * 4);
        gv[q].x = yv.x * (zv.x / (1.f + expf(-zv.x)));
        gv[q].y = yv.y * (zv.y / (1.f + expf(-zv.y)));
        gv[q].z = yv.z * (zv.z / (1.f + expf(-zv.z)));
        gv[q].w = yv.w * (zv.w / (1.f + expf(-zv.w)));
        ss += gv[q].x * gv[q].x + gv[q].y * gv[q].y + gv[q].z * gv[q].z + gv[q].w * gv[q].w;
    }
    ss += __shfl_xor_sync(0xffffffffu, ss, 4);
    ss += __shfl_xor_sync(0xffffffffu, ss, 2);
    ss += __shfl_xor_sync(0xffffffffu, ss, 1);
    const float scale = rsqrtf(ss * (1.f / 128.f) + 1e-5f);
#pragma unroll
    for (int q = 0; q < 4; q++) {
        int k = l8 * 16 + q * 4;
        float4 nwv = *(const float4*)(nw + k);
        Gs[m][k + 0] = gv[q].x * scale * nwv.x;
        Gs[m][k + 1] = gv[q].y * scale * nwv.y;
        Gs[m][k + 2] = gv[q].z * scale * nwv.z;
        Gs[m][k + 3] = gv[q].w * scale * nwv.w;
    }
    __syncthreads();

    // phase 2: micro-tile 2x4 per thread, K=128
    const int tx = tid & 15, ty = tid >> 4;
    float acc[2][4];
#pragma unroll
    for (int i = 0; i < 2; i++)
#pragma unroll
        for (int j = 0; j < 4; j++) acc[i][j] = 0.f;

#pragma unroll
    for (int k4 = 0; k4 < 32; k4++) {
        float4 b0 = *(const float4*)&Ws[k4 * 4 + 0][tx * 4];
        float4 b1 = *(const float4*)&Ws[k4 * 4 + 1][tx * 4];
        float4 b2 = *(const float4*)&Ws[k4 * 4 + 2][tx * 4];
        float4 b3 = *(const float4*)&Ws[k4 * 4 + 3][tx * 4];
#pragma unroll
        for (int i = 0; i < 2; i++) {
            float4 a = *(const float4*)&Gs[ty * 2 + i][k4 * 4];
            acc[i][0] += a.x * b0.x + a.y * b1.x + a.z * b2.x + a.w * b3.x;
            acc[i][1] += a.x * b0.y + a.y * b1.y + a.z * b2.y + a.w * b3.y;
            acc[i][2] += a.x * b0.z + a.y * b1.z + a.z * b2.z + a.w * b3.z;
            acc[i][3] += a.x * b0.w + a.y * b1.w + a.z * b2.w + a.w * b3.w;
        }
    }
#pragma unroll
    for (int i = 0; i < 2; i++) {
        size_t r = (size_t)(m0 + ty * 2 + i) * DM + tx * 4;
        *(float4*)&out[r] = make_float4(acc[i][0], acc[i][1], acc[i][2], acc[i][3]);
    }
}

// ---------------- launch ----------------
extern "C" void kernel_launch(void* const* d_in, const int* in_sizes, int n_in,
                              void* d_out, int out_size) {
    const float* x       = (const float*)d_in[0];
    const float* Win     = (const float*)d_in[1];
    const float* conv_w  = (const float*)d_in[2];
    const float* conv_b  = (const float*)d_in[3];
    const float* dt_bias = (const float*)d_in[4];
    const float* A_log   = (const float*)d_in[5];
    const float* Dp      = (const float*)d_in[6];
    const float* norm_w  = (const float*)d_in[7];
    const float* Wout    = (const float*)d_in[8];
    float* outp = (float*)d_out;

    for (int i = 0; i < 8; i++) {
        int insel  = (i == 0) ? -1 : ((i - 1) & 1);
        int outsel = (i == 7) ? -1 : (i & 1);

        k_inproj<<<dim3(6, 512), 256>>>(x, insel, Win + (size_t)i * DM * NPJ);
        k_dt<<<(MROWS * 2 + 255) / 256, 256>>>(dt_bias + i * NH, A_log + i * NH);
        k_conv<<<dim3(SL / 32, NB), 192>>>(conv_w + (size_t)i * CDIM * 4, conv_b + (size_t)i * CDIM);
        k_scan<<<MROWS * 2 * HD / (SL / 32) / 4 / 32 * 0 + 512, 128>>>(Dp + i * NH);
        k_out<<<MROWS / 32, 256>>>(norm_w + (size_t)i * DIN, Wout + (size_t)i * DIN * DM,
                                   outp, outsel);
    }
}

// round 2
// speedup vs baseline: 6.7868x; 6.7868x over previous
#include <cuda_runtime.h>
#include <cstdint>
#include <math.h>

// ---------------- problem constants ----------------
#define NB   16
#define SL   4096
#define DM   64          // d_model
#define DIN  128         // d_inner
#define DST  32          // d_state
#define NH   2           // heads
#define HD   64          // headdim
#define CDIM 192         // d_inner + 2*d_state
#define NPJ  322         // 2*128 + 2*32 + 2
#define ZST  324         // padded row stride for zxbcdt
#define MROWS (NB*SL)    // 65536
#define CL   64          // chunk length
#define NC   (SL/CL)     // 64 chunks

// ---------------- device scratch ----------------
__device__ float  g_zx [(size_t)MROWS * ZST];
__device__ float  g_xbc[(size_t)MROWS * CDIM];
__device__ float2 g_dtA[(size_t)MROWS * 2];
__device__ float  g_y  [(size_t)MROWS * DIN];
__device__ float  g_buf[2][(size_t)MROWS * DM];
__device__ float  g_hloc [(size_t)NB * NH * NC * HD * DST];   // 16.8MB
__device__ float  g_hin  [(size_t)NB * NH * NC * HD * DST];   // 16.8MB
__device__ float  g_decay[NB * NH * NC];

// ---------------- K1: in-projection GEMM (M=65536, N=322, K=64) ----------------
__global__ __launch_bounds__(256) void k_inproj(const float* __restrict__ xin, int insel,
                                                const float* __restrict__ W) {
    __shared__ float As[128][64];
    __shared__ float Bs[64][64];
    const float* in = (insel >= 0) ? g_buf[insel] : xin;
    const int m0 = blockIdx.y * 128;
    const int n0 = blockIdx.x * 64;
    const int tid = threadIdx.x;

    const float4* A4 = (const float4*)(in + (size_t)m0 * DM);
    float4* As4 = (float4*)&As[0][0];
#pragma unroll
    for (int i = 0; i < 8; i++) As4[i * 256 + tid] = A4[i * 256 + tid];

#pragma unroll
    for (int i = 0; i < 16; i++) {
        int idx = i * 256 + tid;
        int k = idx >> 6, n = idx & 63;
        int gn = n0 + n;
        Bs[k][n] = (gn < NPJ) ? W[k * NPJ + gn] : 0.f;
    }
    __syncthreads();

    const int tx = tid & 15, ty = tid >> 4;
    float acc[8][4];
#pragma unroll
    for (int i = 0; i < 8; i++)
#pragma unroll
        for (int j = 0; j < 4; j++) acc[i][j] = 0.f;

#pragma unroll
    for (int k4 = 0; k4 < 16; k4++) {
        float4 b0 = *(const float4*)&Bs[k4 * 4 + 0][tx * 4];
        float4 b1 = *(const float4*)&Bs[k4 * 4 + 1][tx * 4];
        float4 b2 = *(const float4*)&Bs[k4 * 4 + 2][tx * 4];
        float4 b3 = *(const float4*)&Bs[k4 * 4 + 3][tx * 4];
#pragma unroll
        for (int i = 0; i < 8; i++) {
            float4 a = *(const float4*)&As[ty * 8 + i][k4 * 4];
            acc[i][0] += a.x * b0.x + a.y * b1.x + a.z * b2.x + a.w * b3.x;
            acc[i][1] += a.x * b0.y + a.y * b1.y + a.z * b2.y + a.w * b3.y;
            acc[i][2] += a.x * b0.z + a.y * b1.z + a.z * b2.z + a.w * b3.z;
            acc[i][3] += a.x * b0.w + a.y * b1.w + a.z * b2.w + a.w * b3.w;
        }
    }

    if (n0 + 64 <= NPJ) {
#pragma unroll
        for (int i = 0; i < 8; i++) {
            size_t r = (size_t)(m0 + ty * 8 + i) * ZST + n0 + tx * 4;
            *(float4*)&g_zx[r] = make_float4(acc[i][0], acc[i][1], acc[i][2], acc[i][3]);
        }
    } else {
#pragma unroll
        for (int i = 0; i < 8; i++)
#pragma unroll
            for (int j = 0; j < 4; j++) {
                int gn = n0 + tx * 4 + j;
                if (gn < NPJ) g_zx[(size_t)(m0 + ty * 8 + i) * ZST + gn] = acc[i][j];
            }
    }
}

// ---------------- K1b: dt = softplus(raw + bias), dA = exp(dt * A) ----------------
__global__ __launch_bounds__(256) void k_dt(const float* __restrict__ dt_bias,
                                            const float* __restrict__ A_log) {
    int i = blockIdx.x * 256 + threadIdx.x;
    if (i >= MROWS * 2) return;
    int row = i >> 1, hh = i & 1;
    float v = g_zx[(size_t)row * ZST + 320 + hh] + dt_bias[hh];
    float dt = (v > 15.f) ? v : log1pf(expf(v));
    float A = -expf(A_log[hh]);
    g_dtA[i] = make_float2(dt, expf(dt * A));
}

// ---------------- K2: depthwise causal conv(4) + bias + SiLU ----------------
__global__ __launch_bounds__(192) void k_conv(const float* __restrict__ cw,
                                              const float* __restrict__ cb) {
    __shared__ float s[35][192];
    const int b = blockIdx.y, t0 = blockIdx.x * 32, c = threadIdx.x;
    const float* base = g_zx + (size_t)b * SL * ZST + 128 + c;
#pragma unroll
    for (int r = 0; r < 35; r++) {
        int t = t0 - 3 + r;
        s[r][c] = (t >= 0) ? base[(size_t)t * ZST] : 0.f;
    }
    __syncthreads();
    const float w0 = cw[c * 4 + 0], w1 = cw[c * 4 + 1];
    const float w2 = cw[c * 4 + 2], w3 = cw[c * 4 + 3];
    const float bb = cb[c];
    float* ob = g_xbc + ((size_t)b * SL + t0) * CDIM + c;
#pragma unroll
    for (int tt = 0; tt < 32; tt++) {
        float v = bb + w0 * s[tt][c] + w1 * s[tt + 1][c] + w2 * s[tt + 2][c] + w3 * s[tt + 3][c];
        v = v / (1.f + expf(-v));
        ob[(size_t)tt * CDIM] = v;
    }
}

// ---------------- K3a: chunk-local state (init 0, 64 steps) ----------------
// Block = (chunk c, batch b); 128 threads: h = tid>>6, p = tid&63.
// Each thread holds the 32-dim state in registers. B tile staged in shared.
__global__ __launch_bounds__(128) void k_chunk_state() {
    __shared__ float Bs[CL][DST];
    const int b = blockIdx.y, c = blockIdx.x;
    const int tid = threadIdx.x, h = tid >> 6, p = tid & 63;
    const size_t row0 = (size_t)b * SL + (size_t)c * CL;

#pragma unroll
    for (int i = 0; i < 16; i++) {
        int idx = i * 128 + tid;
        int t = idx >> 5, n = idx & 31;
        Bs[t][n] = g_xbc[(row0 + t) * CDIM + 128 + n];
    }
    __syncthreads();

    const float*  px = g_xbc + row0 * CDIM + h * HD + p;
    const float2* pd = g_dtA + row0 * 2 + h;

    float hs[DST];
#pragma unroll
    for (int n = 0; n < DST; n++) hs[n] = 0.f;
    float cum = 1.f;

#pragma unroll 2
    for (int t = 0; t < CL; t++) {
        float  xv = px[0];
        float2 da = pd[0];
        float  ru = da.x * xv;
        cum *= da.y;
#pragma unroll
        for (int n = 0; n < DST; n += 4) {
            float4 bv = *(const float4*)&Bs[t][n];
            hs[n + 0] = da.y * hs[n + 0] + ru * bv.x;
            hs[n + 1] = da.y * hs[n + 1] + ru * bv.y;
            hs[n + 2] = da.y * hs[n + 2] + ru * bv.z;
            hs[n + 3] = da.y * hs[n + 3] + ru * bv.w;
        }
        px += CDIM; pd += 2;
    }

    float* out = g_hloc + ((((size_t)(b * NH + h) * NC) + c) * HD + p) * DST;
#pragma unroll
    for (int n = 0; n < DST; n += 4)
        *(float4*)&out[n] = make_float4(hs[n], hs[n + 1], hs[n + 2], hs[n + 3]);
    if (p == 0) g_decay[(b * NH + h) * NC + c] = cum;
}

// ---------------- K3b: combine chunk states (sequential over 64 chunks) ----------------
// Block per (b,h); 1024 threads, each owns one float2 of the 64x32 state.
__global__ __launch_bounds__(1024) void k_chunk_combine() {
    const int bh = blockIdx.x;
    const int tid = threadIdx.x;
    const float2* loc = (const float2*)(g_hloc + (size_t)bh * NC * HD * DST) + tid;
    float2*       hin = (float2*)(g_hin + (size_t)bh * NC * HD * DST) + tid;
    const float*  dec = g_decay + bh * NC;

    float2 H = make_float2(0.f, 0.f);
#pragma unroll 4
    for (int c = 0; c < NC; c++) {
        hin[0] = H;
        float2 l = loc[0];
        float  d = dec[c];
        H.x = d * H.x + l.x;
        H.y = d * H.y + l.y;
        loc += HD * DST / 2; hin += HD * DST / 2;
    }
}

// ---------------- K3c: per-chunk scan with incoming state, emits y ----------------
__global__ __launch_bounds__(128) void k_chunk_scan(const float* __restrict__ Dp) {
    __shared__ float Bs[CL][DST];
    __shared__ float Cs[CL][DST];
    const int b = blockIdx.y, c = blockIdx.x;
    const int tid = threadIdx.x, h = tid >> 6, p = tid & 63;
    const size_t row0 = (size_t)b * SL + (size_t)c * CL;

#pragma unroll
    for (int i = 0; i < 16; i++) {
        int idx = i * 128 + tid;
        int t = idx >> 5, n = idx & 31;
        const float* src = &g_xbc[(row0 + t) * CDIM + 128];
        Bs[t][n] = src[n];
        Cs[t][n] = src[32 + n];
    }
    __syncthreads();

    float hs[DST];
    const float* hin = g_hin + ((((size_t)(b * NH + h) * NC) + c) * HD + p) * DST;
#pragma unroll
    for (int n = 0; n < DST; n += 4) {
        float4 v = *(const float4*)&hin[n];
        hs[n] = v.x; hs[n + 1] = v.y; hs[n + 2] = v.z; hs[n + 3] = v.w;
    }

    const float*  px = g_xbc + row0 * CDIM + h * HD + p;
    const float2* pd = g_dtA + row0 * 2 + h;
    float*        py = g_y + row0 * DIN + h * HD + p;
    const float   dp = Dp[h];

#pragma unroll 2
    for (int t = 0; t < CL; t++) {
        float  xv = px[0];
        float2 da = pd[0];
        float  ru = da.x * xv;
        float a0 = 0.f, a1 = 0.f, a2 = 0.f, a3 = 0.f;
#pragma unroll
        for (int n = 0; n < DST; n += 4) {
            float4 bv = *(const float4*)&Bs[t][n];
            float4 cv = *(const float4*)&Cs[t][n];
            hs[n + 0] = da.y * hs[n + 0] + ru * bv.x;
            hs[n + 1] = da.y * hs[n + 1] + ru * bv.y;
            hs[n + 2] = da.y * hs[n + 2] + ru * bv.z;
            hs[n + 3] = da.y * hs[n + 3] + ru * bv.w;
            a0 += hs[n + 0] * cv.x;
            a1 += hs[n + 1] * cv.y;
            a2 += hs[n + 2] * cv.z;
            a3 += hs[n + 3] * cv.w;
        }
        py[0] = (a0 + a1) + (a2 + a3) + dp * xv;
        px += CDIM; pd += 2; py += DIN;
    }
}

// ---------------- K4: gate*silu(z) -> RMSNorm -> out-proj GEMM ----------------
__global__ __launch_bounds__(256) void k_out(const float* __restrict__ nw,
                                             const float* __restrict__ Wout,
                                             float* __restrict__ dout, int outsel) {
    __shared__ float Gs[32][128];
    __shared__ float Ws[128][64];
    float* out = (outsel >= 0) ? g_buf[outsel] : dout;
    const int m0 = blockIdx.x * 32;
    const int tid = threadIdx.x;

    float4* Ws4 = (float4*)&Ws[0][0];
    const float4* W4 = (const float4*)Wout;
#pragma unroll
    for (int i = 0; i < 8; i++) Ws4[i * 256 + tid] = W4[i * 256 + tid];

    const int m = tid >> 3, l8 = tid & 7;
    const float* yrow = g_y + (size_t)(m0 + m) * DIN + l8 * 16;
    const float* zrow = g_zx + (size_t)(m0 + m) * ZST + l8 * 16;
    float4 gv[4];
    float ss = 0.f;
#pragma unroll
    for (int q = 0; q < 4; q++) {
        float4 yv = *(const float4*)(yrow + q * 4);
        float4 zv = *(const float4*)(zrow + q * 4);
        gv[q].x = yv.x * (zv.x / (1.f + expf(-zv.x)));
        gv[q].y = yv.y * (zv.y / (1.f + expf(-zv.y)));
        gv[q].z = yv.z * (zv.z / (1.f + expf(-zv.z)));
        gv[q].w = yv.w * (zv.w / (1.f + expf(-zv.w)));
        ss += gv[q].x * gv[q].x + gv[q].y * gv[q].y + gv[q].z * gv[q].z + gv[q].w * gv[q].w;
    }
    ss += __shfl_xor_sync(0xffffffffu, ss, 4);
    ss += __shfl_xor_sync(0xffffffffu, ss, 2);
    ss += __shfl_xor_sync(0xffffffffu, ss, 1);
    const float scale = rsqrtf(ss * (1.f / 128.f) + 1e-5f);
#pragma unroll
    for (int q = 0; q < 4; q++) {
        int k = l8 * 16 + q * 4;
        float4 nwv = *(const float4*)(nw + k);
        Gs[m][k + 0] = gv[q].x * scale * nwv.x;
        Gs[m][k + 1] = gv[q].y * scale * nwv.y;
        Gs[m][k + 2] = gv[q].z * scale * nwv.z;
        Gs[m][k + 3] = gv[q].w * scale * nwv.w;
    }
    __syncthreads();

    const int tx = tid & 15, ty = tid >> 4;
    float acc[2][4];
#pragma unroll
    for (int i = 0; i < 2; i++)
#pragma unroll
        for (int j = 0; j < 4; j++) acc[i][j] = 0.f;

#pragma unroll
    for (int k4 = 0; k4 < 32; k4++) {
        float4 b0 = *(const float4*)&Ws[k4 * 4 + 0][tx * 4];
        float4 b1 = *(const float4*)&Ws[k4 * 4 + 1][tx * 4];
        float4 b2 = *(const float4*)&Ws[k4 * 4 + 2][tx * 4];
        float4 b3 = *(const float4*)&Ws[k4 * 4 + 3][tx * 4];
#pragma unroll
        for (int i = 0; i < 2; i++) {
            float4 a = *(const float4*)&Gs[ty * 2 + i][k4 * 4];
            acc[i][0] += a.x * b0.x + a.y * b1.x + a.z * b2.x + a.w * b3.x;
            acc[i][1] += a.x * b0.y + a.y * b1.y + a.z * b2.y + a.w * b3.y;
            acc[i][2] += a.x * b0.z + a.y * b1.z + a.z * b2.z + a.w * b3.z;
            acc[i][3] += a.x * b0.w + a.y * b1.w + a.z * b2.w + a.w * b3.w;
        }
    }
#pragma unroll
    for (int i = 0; i < 2; i++) {
        size_t r = (size_t)(m0 + ty * 2 + i) * DM + tx * 4;
        *(float4*)&out[r] = make_float4(acc[i][0], acc[i][1], acc[i][2], acc[i][3]);
    }
}

// ---------------- launch ----------------
extern "C" void kernel_launch(void* const* d_in, const int* in_sizes, int n_in,
                              void* d_out, int out_size) {
    const float* x       = (const float*)d_in[0];
    const float* Win     = (const float*)d_in[1];
    const float* conv_w  = (const float*)d_in[2];
    const float* conv_b  = (const float*)d_in[3];
    const float* dt_bias = (const float*)d_in[4];
    const float* A_log   = (const float*)d_in[5];
    const float* Dp      = (const float*)d_in[6];
    const float* norm_w  = (const float*)d_in[7];
    const float* Wout    = (const float*)d_in[8];
    float* outp = (float*)d_out;

    for (int i = 0; i < 8; i++) {
        int insel  = (i == 0) ? -1 : ((i - 1) & 1);
        int outsel = (i == 7) ? -1 : (i & 1);

        k_inproj<<<dim3(6, 512), 256>>>(x, insel, Win + (size_t)i * DM * NPJ);
        k_dt<<<(MROWS * 2 + 255) / 256, 256>>>(dt_bias + i * NH, A_log + i * NH);
        k_conv<<<dim3(SL / 32, NB), 192>>>(conv_w + (size_t)i * CDIM * 4, conv_b + (size_t)i * CDIM);
        k_chunk_state<<<dim3(NC, NB), 128>>>();
        k_chunk_combine<<<NB * NH, 1024>>>();
        k_chunk_scan<<<dim3(NC, NB), 128>>>(Dp + i * NH);
        k_out<<<MROWS / 32, 256>>>(norm_w + (size_t)i * DIN, Wout + (size_t)i * DIN * DM,
                                   outp, outsel);
    }
}

// round 3
// speedup vs baseline: 7.0102x; 1.0329x over previous
#include <cuda_runtime.h>
#include <cstdint>
#include <math.h>

// ---------------- problem constants ----------------
#define NB   16
#define SL   4096
#define DM   64          // d_model
#define DIN  128         // d_inner
#define DST  32          // d_state
#define NH   2           // heads
#define HD   64          // headdim
#define CDIM 192         // d_inner + 2*d_state
#define NPJ  322         // 2*128 + 2*32 + 2
#define ZST  324         // padded row stride for zxbcdt
#define MROWS (NB*SL)    // 65536
#define CL   64          // chunk length
#define NC   (SL/CL)     // 64 chunks
#define HSZ  (HD*DST)    // 2048 floats per (b,h,chunk) state

// ---------------- device scratch ----------------
__device__ float  g_zx [(size_t)MROWS * ZST];
__device__ float  g_xbc[(size_t)MROWS * CDIM];
__device__ float2 g_dtA[(size_t)MROWS * 2];
__device__ float  g_cd [(size_t)MROWS * 2];     // in-chunk cumulative decay per (row, h)
__device__ float  g_y  [(size_t)MROWS * DIN];
__device__ float  g_buf[2][(size_t)MROWS * DM];
__device__ float  g_hloc[(size_t)NB * NH * NC * HSZ];
__device__ float  g_hin [(size_t)NB * NH * NC * HSZ];

// ---------------- K1: in-projection GEMM (M=65536, N=322, K=64) + fused dt ----------------
__global__ __launch_bounds__(256) void k_inproj(const float* __restrict__ xin, int insel,
                                                const float* __restrict__ W,
                                                const float* __restrict__ dt_bias,
                                                const float* __restrict__ A_log) {
    __shared__ float As[128][64];
    __shared__ float Bs[64][64];
    const float* in = (insel >= 0) ? g_buf[insel] : xin;
    const int m0 = blockIdx.y * 128;
    const int n0 = blockIdx.x * 64;
    const int tid = threadIdx.x;

    const float4* A4 = (const float4*)(in + (size_t)m0 * DM);
    float4* As4 = (float4*)&As[0][0];
#pragma unroll
    for (int i = 0; i < 8; i++) As4[i * 256 + tid] = A4[i * 256 + tid];

#pragma unroll
    for (int i = 0; i < 16; i++) {
        int idx = i * 256 + tid;
        int k = idx >> 6, n = idx & 63;
        int gn = n0 + n;
        Bs[k][n] = (gn < NPJ) ? W[k * NPJ + gn] : 0.f;
    }
    __syncthreads();

    const int tx = tid & 15, ty = tid >> 4;
    float acc[8][4];
#pragma unroll
    for (int i = 0; i < 8; i++)
#pragma unroll
        for (int j = 0; j < 4; j++) acc[i][j] = 0.f;

#pragma unroll
    for (int k4 = 0; k4 < 16; k4++) {
        float4 b0 = *(const float4*)&Bs[k4 * 4 + 0][tx * 4];
        float4 b1 = *(const float4*)&Bs[k4 * 4 + 1][tx * 4];
        float4 b2 = *(const float4*)&Bs[k4 * 4 + 2][tx * 4];
        float4 b3 = *(const float4*)&Bs[k4 * 4 + 3][tx * 4];
#pragma unroll
        for (int i = 0; i < 8; i++) {
            float4 a = *(const float4*)&As[ty * 8 + i][k4 * 4];
            acc[i][0] += a.x * b0.x + a.y * b1.x + a.z * b2.x + a.w * b3.x;
            acc[i][1] += a.x * b0.y + a.y * b1.y + a.z * b2.y + a.w * b3.y;
            acc[i][2] += a.x * b0.z + a.y * b1.z + a.z * b2.z + a.w * b3.z;
            acc[i][3] += a.x * b0.w + a.y * b1.w + a.z * b2.w + a.w * b3.w;
        }
    }

    if (n0 + 64 <= NPJ) {
#pragma unroll
        for (int i = 0; i < 8; i++) {
            size_t r = (size_t)(m0 + ty * 8 + i) * ZST + n0 + tx * 4;
            *(float4*)&g_zx[r] = make_float4(acc[i][0], acc[i][1], acc[i][2], acc[i][3]);
        }
    } else {
        // n0 == 320: cols 320,321 are the raw dt logits -> fused softplus + exp
        const float A0 = -expf(A_log[0]), A1 = -expf(A_log[1]);
        const float b0v = dt_bias[0], b1v = dt_bias[1];
#pragma unroll
        for (int i = 0; i < 8; i++)
#pragma unroll
            for (int j = 0; j < 4; j++) {
                int gn = n0 + tx * 4 + j;
                if (gn == 320 || gn == 321) {
                    int hh = gn - 320;
                    float v = acc[i][j] + (hh ? b1v : b0v);
                    float dt = (v > 15.f) ? v : log1pf(expf(v));
                    float A = hh ? A1 : A0;
                    g_dtA[(size_t)(m0 + ty * 8 + i) * 2 + hh] = make_float2(dt, expf(dt * A));
                }
            }
    }
}

// ---------------- K2: depthwise causal conv(4) + bias + SiLU ----------------
__global__ __launch_bounds__(192) void k_conv(const float* __restrict__ cw,
                                              const float* __restrict__ cb) {
    __shared__ float s[35][192];
    const int b = blockIdx.y, t0 = blockIdx.x * 32, c = threadIdx.x;
    const float* base = g_zx + (size_t)b * SL * ZST + 128 + c;
#pragma unroll
    for (int r = 0; r < 35; r++) {
        int t = t0 - 3 + r;
        s[r][c] = (t >= 0) ? base[(size_t)t * ZST] : 0.f;
    }
    __syncthreads();
    const float w0 = cw[c * 4 + 0], w1 = cw[c * 4 + 1];
    const float w2 = cw[c * 4 + 2], w3 = cw[c * 4 + 3];
    const float bb = cb[c];
    float* ob = g_xbc + ((size_t)b * SL + t0) * CDIM + c;
#pragma unroll
    for (int tt = 0; tt < 32; tt++) {
        float v = bb + w0 * s[tt][c] + w1 * s[tt + 1][c] + w2 * s[tt + 2][c] + w3 * s[tt + 3][c];
        v = v / (1.f + expf(-v));
        ob[(size_t)tt * CDIM] = v;
    }
}

// ---------------- K3a: single-pass chunk scan from zero state ----------------
// Emits y_local = C.h_loc + Dp*x, chunk-final state h_loc, per-step cumdecay.
__global__ __launch_bounds__(128) void k_scanA(const float* __restrict__ Dp) {
    __shared__ float Bs[CL][DST];
    __shared__ float Cs[CL][DST];
    const int b = blockIdx.y, c = blockIdx.x;
    const int tid = threadIdx.x, h = tid >> 6, p = tid & 63;
    const size_t row0 = (size_t)b * SL + (size_t)c * CL;

#pragma unroll
    for (int i = 0; i < 16; i++) {
        int idx = i * 128 + tid;
        int t = idx >> 5, n = idx & 31;
        const float* src = &g_xbc[(row0 + t) * CDIM + 128];
        Bs[t][n] = src[n];
        Cs[t][n] = src[32 + n];
    }
    __syncthreads();

    const float*  px = g_xbc + row0 * CDIM + h * HD + p;
    const float2* pd = g_dtA + row0 * 2 + h;
    float*        py = g_y + row0 * DIN + h * HD + p;
    float*        pc = g_cd + row0 * 2 + h;
    const float   dp = Dp[h];

    float hs[DST];
#pragma unroll
    for (int n = 0; n < DST; n++) hs[n] = 0.f;
    float cum = 1.f;

#pragma unroll 2
    for (int t = 0; t < CL; t++) {
        float  xv = px[0];
        float2 da = pd[0];
        float  ru = da.x * xv;
        cum *= da.y;
        float a0 = 0.f, a1 = 0.f, a2 = 0.f, a3 = 0.f;
#pragma unroll
        for (int n = 0; n < DST; n += 4) {
            float4 bv = *(const float4*)&Bs[t][n];
            float4 cv = *(const float4*)&Cs[t][n];
            hs[n + 0] = da.y * hs[n + 0] + ru * bv.x;
            hs[n + 1] = da.y * hs[n + 1] + ru * bv.y;
            hs[n + 2] = da.y * hs[n + 2] + ru * bv.z;
            hs[n + 3] = da.y * hs[n + 3] + ru * bv.w;
            a0 += hs[n + 0] * cv.x;
            a1 += hs[n + 1] * cv.y;
            a2 += hs[n + 2] * cv.z;
            a3 += hs[n + 3] * cv.w;
        }
        py[0] = (a0 + a1) + (a2 + a3) + dp * xv;
        if (p == 0) pc[0] = cum;
        px += CDIM; pd += 2; py += DIN; pc += 2;
    }

    float* out = g_hloc + ((((size_t)(b * NH + h) * NC) + c) * HD + p) * DST;
#pragma unroll
    for (int n = 0; n < DST; n += 4)
        *(float4*)&out[n] = make_float4(hs[n], hs[n + 1], hs[n + 2], hs[n + 3]);
}

// ---------------- K3b: combine chunk states (sequential over 64 chunks) ----------------
// 8 blocks of 256 threads per (b,h); each thread owns one float of the 64x32 state.
__global__ __launch_bounds__(256) void k_combine() {
    const int bh  = blockIdx.x >> 3;
    const int sub = blockIdx.x & 7;
    const int bb  = bh >> 1, hh = bh & 1;
    const int off = sub * 256 + threadIdx.x;

    const float* loc = g_hloc + (size_t)bh * NC * HSZ + off;
    float*       hin = g_hin  + (size_t)bh * NC * HSZ + off;
    const float* cdb = g_cd + ((size_t)bb * SL + CL - 1) * 2 + hh;

    float H = 0.f;
#pragma unroll 4
    for (int c = 0; c < NC; c++) {
        hin[0] = H;
        float d = __ldg(cdb);
        H = d * H + loc[0];
        loc += HSZ; hin += HSZ; cdb += (size_t)CL * 2;
    }
}

// ---------------- K3c: cross-chunk correction  y += cumdecay * (C . H_in) ----------------
__global__ __launch_bounds__(128) void k_corr() {
    __shared__ float Cs[CL][DST];
    __shared__ float cds[CL][2];
    const int b = blockIdx.y, c = blockIdx.x;
    const int tid = threadIdx.x, h = tid >> 6, p = tid & 63;
    const size_t row0 = (size_t)b * SL + (size_t)c * CL;

#pragma unroll
    for (int i = 0; i < 16; i++) {
        int idx = i * 128 + tid;
        int t = idx >> 5, n = idx & 31;
        Cs[t][n] = g_xbc[(row0 + t) * CDIM + 160 + n];
    }
    if (tid < CL) {
        cds[tid][0] = g_cd[(row0 + tid) * 2 + 0];
        cds[tid][1] = g_cd[(row0 + tid) * 2 + 1];
    }
    __syncthreads();

    float v[DST];
    const float* hin = g_hin + ((((size_t)(b * NH + h) * NC) + c) * HD + p) * DST;
#pragma unroll
    for (int n = 0; n < DST; n += 4) {
        float4 t4 = *(const float4*)&hin[n];
        v[n] = t4.x; v[n + 1] = t4.y; v[n + 2] = t4.z; v[n + 3] = t4.w;
    }

    float* py = g_y + row0 * DIN + h * HD + p;
#pragma unroll 2
    for (int t = 0; t < CL; t++) {
        float a0 = 0.f, a1 = 0.f, a2 = 0.f, a3 = 0.f;
#pragma unroll
        for (int n = 0; n < DST; n += 4) {
            float4 cv = *(const float4*)&Cs[t][n];
            a0 += v[n + 0] * cv.x;
            a1 += v[n + 1] * cv.y;
            a2 += v[n + 2] * cv.z;
            a3 += v[n + 3] * cv.w;
        }
        py[0] += cds[t][h] * ((a0 + a1) + (a2 + a3));
        py += DIN;
    }
}

// ---------------- K4: gate*silu(z) -> RMSNorm -> out-proj GEMM ----------------
__global__ __launch_bounds__(256) void k_out(const float* __restrict__ nw,
                                             const float* __restrict__ Wout,
                                             float* __restrict__ dout, int outsel) {
    __shared__ float Gs[32][128];
    __shared__ float Ws[128][64];
    float* out = (outsel >= 0) ? g_buf[outsel] : dout;
    const int m0 = blockIdx.x * 32;
    const int tid = threadIdx.x;

    float4* Ws4 = (float4*)&Ws[0][0];
    const float4* W4 = (const float4*)Wout;
#pragma unroll
    for (int i = 0; i < 8; i++) Ws4[i * 256 + tid] = W4[i * 256 + tid];

    const int m = tid >> 3, l8 = tid & 7;
    const float* yrow = g_y + (size_t)(m0 + m) * DIN + l8 * 16;
    const float* zrow = g_zx + (size_t)(m0 + m) * ZST + l8 * 16;
    float4 gv[4];
    float ss = 0.f;
#pragma unroll
    for (int q = 0; q < 4; q++) {
        float4 yv = *(const float4*)(yrow + q * 4);
        float4 zv = *(const float4*)(zrow + q * 4);
        gv[q].x = yv.x * (zv.x / (1.f + expf(-zv.x)));
        gv[q].y = yv.y * (zv.y / (1.f + expf(-zv.y)));
        gv[q].z = yv.z * (zv.z / (1.f + expf(-zv.z)));
        gv[q].w = yv.w * (zv.w / (1.f + expf(-zv.w)));
        ss += gv[q].x * gv[q].x + gv[q].y * gv[q].y + gv[q].z * gv[q].z + gv[q].w * gv[q].w;
    }
    ss += __shfl_xor_sync(0xffffffffu, ss, 4);
    ss += __shfl_xor_sync(0xffffffffu, ss, 2);
    ss += __shfl_xor_sync(0xffffffffu, ss, 1);
    const float scale = rsqrtf(ss * (1.f / 128.f) + 1e-5f);
#pragma unroll
    for (int q = 0; q < 4; q++) {
        int k = l8 * 16 + q * 4;
        float4 nwv = *(const float4*)(nw + k);
        Gs[m][k + 0] = gv[q].x * scale * nwv.x;
        Gs[m][k + 1] = gv[q].y * scale * nwv.y;
        Gs[m][k + 2] = gv[q].z * scale * nwv.z;
        Gs[m][k + 3] = gv[q].w * scale * nwv.w;
    }
    __syncthreads();

    const int tx = tid & 15, ty = tid >> 4;
    float acc[2][4];
#pragma unroll
    for (int i = 0; i < 2; i++)
#pragma unroll
        for (int j = 0; j < 4; j++) acc[i][j] = 0.f;

#pragma unroll
    for (int k4 = 0; k4 < 32; k4++) {
        float4 b0 = *(const float4*)&Ws[k4 * 4 + 0][tx * 4];
        float4 b1 = *(const float4*)&Ws[k4 * 4 + 1][tx * 4];
        float4 b2 = *(const float4*)&Ws[k4 * 4 + 2][tx * 4];
        float4 b3 = *(const float4*)&Ws[k4 * 4 + 3][tx * 4];
#pragma unroll
        for (int i = 0; i < 2; i++) {
            float4 a = *(const float4*)&Gs[ty * 2 + i][k4 * 4];
            acc[i][0] += a.x * b0.x + a.y * b1.x + a.z * b2.x + a.w * b3.x;
            acc[i][1] += a.x * b0.y + a.y * b1.y + a.z * b2.y + a.w * b3.y;
            acc[i][2] += a.x * b0.z + a.y * b1.z + a.z * b2.z + a.w * b3.z;
            acc[i][3] += a.x * b0.w + a.y * b1.w + a.z * b2.w + a.w * b3.w;
        }
    }
#pragma unroll
    for (int i = 0; i < 2; i++) {
        size_t r = (size_t)(m0 + ty * 2 + i) * DM + tx * 4;
        *(float4*)&out[r] = make_float4(acc[i][0], acc[i][1], acc[i][2], acc[i][3]);
    }
}

// ---------------- launch ----------------
extern "C" void kernel_launch(void* const* d_in, const int* in_sizes, int n_in,
                              void* d_out, int out_size) {
    const float* x       = (const float*)d_in[0];
    const float* Win     = (const float*)d_in[1];
    const float* conv_w  = (const float*)d_in[2];
    const float* conv_b  = (const float*)d_in[3];
    const float* dt_bias = (const float*)d_in[4];
    const float* A_log   = (const float*)d_in[5];
    const float* Dp      = (const float*)d_in[6];
    const float* norm_w  = (const float*)d_in[7];
    const float* Wout    = (const float*)d_in[8];
    float* outp = (float*)d_out;

    for (int i = 0; i < 8; i++) {
        int insel  = (i == 0) ? -1 : ((i - 1) & 1);
        int outsel = (i == 7) ? -1 : (i & 1);

        k_inproj<<<dim3(6, 512), 256>>>(x, insel, Win + (size_t)i * DM * NPJ,
                                        dt_bias + i * NH, A_log + i * NH);
        k_conv<<<dim3(SL / 32, NB), 192>>>(conv_w + (size_t)i * CDIM * 4,
                                           conv_b + (size_t)i * CDIM);
        k_scanA<<<dim3(NC, NB), 128>>>(Dp + i * NH);
        k_combine<<<NB * NH * 8, 256>>>();
        k_corr<<<dim3(NC, NB), 128>>>();
        k_out<<<MROWS / 32, 256>>>(norm_w + (size_t)i * DIN, Wout + (size_t)i * DIN * DM,
                                   outp, outsel);
    }
}

// round 4
// speedup vs baseline: 7.0113x; 1.0002x over previous
#include <cuda_runtime.h>
#include <cstdint>
#include <math.h>

// ---------------- problem constants ----------------
#define NB   16
#define SL   4096
#define DM   64          // d_model
#define DIN  128         // d_inner
#define DST  32          // d_state
#define NH   2           // heads
#define HD   64          // headdim
#define CDIM 192         // d_inner + 2*d_state
#define NPJ  322         // 2*128 + 2*32 + 2
#define ZST  324         // padded row stride for zxbcdt
#define MROWS (NB*SL)    // 65536
#define CL   64          // chunk length
#define NC   (SL/CL)     // 64 chunks
#define HSZ  (HD*DST)    // 2048 floats per (b,h,chunk) state

// ---------------- device scratch ----------------
__device__ float  g_zx [(size_t)MROWS * ZST];
__device__ float  g_xbc[(size_t)MROWS * CDIM];
__device__ float2 g_dtA[(size_t)MROWS * 2];
__device__ float  g_cd [(size_t)MROWS * 2];     // in-chunk cumulative decay per (row, h)
__device__ float  g_y  [(size_t)MROWS * DIN];
__device__ float  g_buf[2][(size_t)MROWS * DM];
__device__ float  g_hloc[(size_t)NB * NH * NC * HSZ];
__device__ float  g_hin [(size_t)NB * NH * NC * HSZ];

// ---------------- K1: in-projection GEMM (M=65536, N=322, K=64) + fused dt ----------------
// 128 threads, block tile 128x64, micro-tile 8x8, A staged transposed.
__global__ __launch_bounds__(128) void k_inproj(const float* __restrict__ xin, int insel,
                                                const float* __restrict__ W,
                                                const float* __restrict__ dt_bias,
                                                const float* __restrict__ A_log) {
    __shared__ float Ast[64][128];   // [k][m] transposed
    __shared__ float Bs[64][64];
    const float* in = (insel >= 0) ? g_buf[insel] : xin;
    const int m0 = blockIdx.y * 128;
    const int n0 = blockIdx.x * 64;
    const int tid = threadIdx.x;

    // A: one row per thread, scatter into transposed layout (STS conflict-free:
    // lanes write consecutive m at fixed k).
    {
        const float4* Arow = (const float4*)(in + (size_t)(m0 + tid) * DM);
#pragma unroll
        for (int q = 0; q < 16; q++) {
            float4 v = Arow[q];
            Ast[q * 4 + 0][tid] = v.x;
            Ast[q * 4 + 1][tid] = v.y;
            Ast[q * 4 + 2][tid] = v.z;
            Ast[q * 4 + 3][tid] = v.w;
        }
    }
    // B tile 64x64 (stride NPJ in gmem), predicated on gn < NPJ
#pragma unroll
    for (int i = 0; i < 32; i++) {
        int idx = i * 128 + tid;
        int k = idx >> 6, n = idx & 63;
        int gn = n0 + n;
        Bs[k][n] = (gn < NPJ) ? W[k * NPJ + gn] : 0.f;
    }
    __syncthreads();

    const int tx = tid & 7, ty = tid >> 3;   // 8 x 16
    float acc[8][8];
#pragma unroll
    for (int i = 0; i < 8; i++)
#pragma unroll
        for (int j = 0; j < 8; j++) acc[i][j] = 0.f;

#pragma unroll 8
    for (int k = 0; k < 64; k++) {
        float4 a0 = *(const float4*)&Ast[k][ty * 8 + 0];
        float4 a1 = *(const float4*)&Ast[k][ty * 8 + 4];
        float4 b0 = *(const float4*)&Bs[k][tx * 8 + 0];
        float4 b1 = *(const float4*)&Bs[k][tx * 8 + 4];
        float av[8] = {a0.x, a0.y, a0.z, a0.w, a1.x, a1.y, a1.z, a1.w};
        float bv[8] = {b0.x, b0.y, b0.z, b0.w, b1.x, b1.y, b1.z, b1.w};
#pragma unroll
        for (int i = 0; i < 8; i++)
#pragma unroll
            for (int j = 0; j < 8; j++) acc[i][j] += av[i] * bv[j];
    }

    if (n0 + 64 <= NPJ) {
#pragma unroll
        for (int i = 0; i < 8; i++) {
            size_t r = (size_t)(m0 + ty * 8 + i) * ZST + n0 + tx * 8;
            *(float4*)&g_zx[r + 0] = make_float4(acc[i][0], acc[i][1], acc[i][2], acc[i][3]);
            *(float4*)&g_zx[r + 4] = make_float4(acc[i][4], acc[i][5], acc[i][6], acc[i][7]);
        }
    } else if (tx == 0) {
        // n0 == 320: cols 320,321 are raw dt logits -> fused softplus + exp(dt*A)
        const float A0 = -expf(A_log[0]), A1 = -expf(A_log[1]);
        const float b0v = dt_bias[0], b1v = dt_bias[1];
#pragma unroll
        for (int i = 0; i < 8; i++) {
#pragma unroll
            for (int hh = 0; hh < 2; hh++) {
                float v = acc[i][hh] + (hh ? b1v : b0v);
                float dt = (v > 15.f) ? v : log1pf(expf(v));
                float A = hh ? A1 : A0;
                g_dtA[(size_t)(m0 + ty * 8 + i) * 2 + hh] = make_float2(dt, expf(dt * A));
            }
        }
    }
}

// ---------------- K2: depthwise causal conv(4) + bias + SiLU ----------------
__global__ __launch_bounds__(192) void k_conv(const float* __restrict__ cw,
                                              const float* __restrict__ cb) {
    __shared__ float s[35][192];
    const int b = blockIdx.y, t0 = blockIdx.x * 32, c = threadIdx.x;
    const float* base = g_zx + (size_t)b * SL * ZST + 128 + c;
#pragma unroll
    for (int r = 0; r < 35; r++) {
        int t = t0 - 3 + r;
        s[r][c] = (t >= 0) ? base[(size_t)t * ZST] : 0.f;
    }
    __syncthreads();
    const float w0 = cw[c * 4 + 0], w1 = cw[c * 4 + 1];
    const float w2 = cw[c * 4 + 2], w3 = cw[c * 4 + 3];
    const float bb = cb[c];
    float* ob = g_xbc + ((size_t)b * SL + t0) * CDIM + c;
#pragma unroll
    for (int tt = 0; tt < 32; tt++) {
        float v = bb + w0 * s[tt][c] + w1 * s[tt + 1][c] + w2 * s[tt + 2][c] + w3 * s[tt + 3][c];
        v = v / (1.f + expf(-v));
        ob[(size_t)tt * CDIM] = v;
    }
}

// ---------------- K3a: single-pass chunk scan from zero state ----------------
__global__ __launch_bounds__(128) void k_scanA(const float* __restrict__ Dp) {
    __shared__ float Bs[CL][DST];
    __shared__ float Cs[CL][DST];
    const int b = blockIdx.y, c = blockIdx.x;
    const int tid = threadIdx.x, h = tid >> 6, p = tid & 63;
    const size_t row0 = (size_t)b * SL + (size_t)c * CL;

#pragma unroll
    for (int i = 0; i < 16; i++) {
        int idx = i * 128 + tid;
        int t = idx >> 5, n = idx & 31;
        const float* src = &g_xbc[(row0 + t) * CDIM + 128];
        Bs[t][n] = src[n];
        Cs[t][n] = src[32 + n];
    }
    __syncthreads();

    const float*  px = g_xbc + row0 * CDIM + h * HD + p;
    const float2* pd = g_dtA + row0 * 2 + h;
    float*        py = g_y + row0 * DIN + h * HD + p;
    float*        pc = g_cd + row0 * 2 + h;
    const float   dp = Dp[h];

    float hs[DST];
#pragma unroll
    for (int n = 0; n < DST; n++) hs[n] = 0.f;
    float cum = 1.f;

#pragma unroll 2
    for (int t = 0; t < CL; t++) {
        float  xv = px[0];
        float2 da = pd[0];
        float  ru = da.x * xv;
        cum *= da.y;
        float a0 = 0.f, a1 = 0.f, a2 = 0.f, a3 = 0.f;
#pragma unroll
        for (int n = 0; n < DST; n += 4) {
            float4 bv = *(const float4*)&Bs[t][n];
            float4 cv = *(const float4*)&Cs[t][n];
            hs[n + 0] = da.y * hs[n + 0] + ru * bv.x;
            hs[n + 1] = da.y * hs[n + 1] + ru * bv.y;
            hs[n + 2] = da.y * hs[n + 2] + ru * bv.z;
            hs[n + 3] = da.y * hs[n + 3] + ru * bv.w;
            a0 += hs[n + 0] * cv.x;
            a1 += hs[n + 1] * cv.y;
            a2 += hs[n + 2] * cv.z;
            a3 += hs[n + 3] * cv.w;
        }
        py[0] = (a0 + a1) + (a2 + a3) + dp * xv;
        if (p == 0) pc[0] = cum;
        px += CDIM; pd += 2; py += DIN; pc += 2;
    }

    float* out = g_hloc + ((((size_t)(b * NH + h) * NC) + c) * HD + p) * DST;
#pragma unroll
    for (int n = 0; n < DST; n += 4)
        *(float4*)&out[n] = make_float4(hs[n], hs[n + 1], hs[n + 2], hs[n + 3]);
}

// ---------------- K3b: combine chunk states (sequential over 64 chunks) ----------------
// 8 blocks x 256 threads per (b,h); 8-deep prefetch pipeline hides load latency.
__global__ __launch_bounds__(256) void k_combine() {
    __shared__ float ds[NC];
    const int bh  = blockIdx.x >> 3;
    const int sub = blockIdx.x & 7;
    const int bb  = bh >> 1, hh = bh & 1;
    if (threadIdx.x < NC)
        ds[threadIdx.x] = g_cd[((size_t)bb * SL + threadIdx.x * CL + CL - 1) * 2 + hh];
    __syncthreads();

    const int off = sub * 256 + threadIdx.x;
    const float* loc = g_hloc + (size_t)bh * NC * HSZ + off;
    float*       hin = g_hin  + (size_t)bh * NC * HSZ + off;

    float H = 0.f;
    float buf[8];
#pragma unroll
    for (int j = 0; j < 8; j++) buf[j] = loc[(size_t)j * HSZ];

#pragma unroll
    for (int cb = 0; cb < NC; cb += 8) {
        float nbuf[8];
        if (cb + 8 < NC) {
#pragma unroll
            for (int j = 0; j < 8; j++) nbuf[j] = loc[(size_t)(cb + 8 + j) * HSZ];
        } else {
#pragma unroll
            for (int j = 0; j < 8; j++) nbuf[j] = 0.f;
        }
#pragma unroll
        for (int j = 0; j < 8; j++) {
            hin[(size_t)(cb + j) * HSZ] = H;
            H = ds[cb + j] * H + buf[j];
        }
#pragma unroll
        for (int j = 0; j < 8; j++) buf[j] = nbuf[j];
    }
}

// ---------------- K4: fused cross-chunk correction + gate*silu(z) + RMSNorm + out-proj ----
__global__ __launch_bounds__(256) void k_out(const float* __restrict__ nw,
                                             const float* __restrict__ Wout,
                                             float* __restrict__ dout, int outsel) {
    __shared__ float Ws[128][64];    // 32KB
    __shared__ float Yc[32][128];    // 16KB: corrected y, then normalized acts
    __shared__ float Cs[32][32];     // 4KB
    __shared__ float cds[32][2];
    float* out = (outsel >= 0) ? g_buf[outsel] : dout;
    const int m0 = blockIdx.x * 32;
    const int b  = m0 >> 12;                 // / SL
    const int c  = (m0 & (SL - 1)) >> 6;     // chunk index
    const int tid = threadIdx.x;

    // Wout tile: 128x64 contiguous
    {
        float4* Ws4 = (float4*)&Ws[0][0];
        const float4* W4 = (const float4*)Wout;
#pragma unroll
        for (int i = 0; i < 8; i++) Ws4[i * 256 + tid] = W4[i * 256 + tid];
    }
    // C rows + cumdecay for these 32 rows
    {
        int t = tid >> 3, n = (tid & 7) * 4;
        *(float4*)&Cs[t][n] = *(const float4*)&g_xbc[(size_t)(m0 + t) * CDIM + 160 + n];
        if (tid < 32) {
            cds[tid][0] = g_cd[(size_t)(m0 + tid) * 2 + 0];
            cds[tid][1] = g_cd[(size_t)(m0 + tid) * 2 + 1];
        }
    }
    __syncthreads();

    // ---- phase A: correction. thread = (column k, row-half rh) ----
    {
        const int k = tid & 127, rh = tid >> 7;
        const int h = k >> 6, p = k & 63;
        float Hr[DST];
        const float* hin = g_hin + ((((size_t)(b * NH + h) * NC) + c) * HD + p) * DST;
#pragma unroll
        for (int n = 0; n < DST; n += 4) {
            float4 v = *(const float4*)&hin[n];
            Hr[n] = v.x; Hr[n + 1] = v.y; Hr[n + 2] = v.z; Hr[n + 3] = v.w;
        }
        const float* py = g_y + (size_t)(m0 + rh * 16) * DIN + k;
#pragma unroll 4
        for (int t = 0; t < 16; t++) {
            int row = rh * 16 + t;
            float a0 = 0.f, a1 = 0.f, a2 = 0.f, a3 = 0.f;
#pragma unroll
            for (int n = 0; n < DST; n += 4) {
                float4 cv = *(const float4*)&Cs[row][n];
                a0 += Hr[n + 0] * cv.x;
                a1 += Hr[n + 1] * cv.y;
                a2 += Hr[n + 2] * cv.z;
                a3 += Hr[n + 3] * cv.w;
            }
            Yc[row][k] = py[(size_t)t * DIN] + cds[row][h] * ((a0 + a1) + (a2 + a3));
        }
    }
    __syncthreads();

    // ---- phase B: gate * silu(z), RMSNorm (in-place in Yc) ----
    {
        const int m = tid >> 3, l8 = tid & 7;
        const float* zrow = g_zx + (size_t)(m0 + m) * ZST + l8 * 16;
        float4 gv[4];
        float ss = 0.f;
#pragma unroll
        for (int q = 0; q < 4; q++) {
            float4 yv = *(const float4*)&Yc[m][l8 * 16 + q * 4];
            float4 zv = *(const float4*)(zrow + q * 4);
            gv[q].x = yv.x * (zv.x / (1.f + expf(-zv.x)));
            gv[q].y = yv.y * (zv.y / (1.f + expf(-zv.y)));
            gv[q].z = yv.z * (zv.z / (1.f + expf(-zv.z)));
            gv[q].w = yv.w * (zv.w / (1.f + expf(-zv.w)));
            ss += gv[q].x * gv[q].x + gv[q].y * gv[q].y + gv[q].z * gv[q].z + gv[q].w * gv[q].w;
        }
        ss += __shfl_xor_sync(0xffffffffu, ss, 4);
        ss += __shfl_xor_sync(0xffffffffu, ss, 2);
        ss += __shfl_xor_sync(0xffffffffu, ss, 1);
        const float scale = rsqrtf(ss * (1.f / 128.f) + 1e-5f);
#pragma unroll
        for (int q = 0; q < 4; q++) {
            int k = l8 * 16 + q * 4;
            float4 nwv = *(const float4*)(nw + k);
            Yc[m][k + 0] = gv[q].x * scale * nwv.x;
            Yc[m][k + 1] = gv[q].y * scale * nwv.y;
            Yc[m][k + 2] = gv[q].z * scale * nwv.z;
            Yc[m][k + 3] = gv[q].w * scale * nwv.w;
        }
    }
    __syncthreads();

    // ---- phase C: 32x64 GEMM, K=128 ----
    const int tx = tid & 15, ty = tid >> 4;
    float acc[2][4];
#pragma unroll
    for (int i = 0; i < 2; i++)
#pragma unroll
        for (int j = 0; j < 4; j++) acc[i][j] = 0.f;

#pragma unroll
    for (int k4 = 0; k4 < 32; k4++) {
        float4 b0 = *(const float4*)&Ws[k4 * 4 + 0][tx * 4];
        float4 b1 = *(const float4*)&Ws[k4 * 4 + 1][tx * 4];
        float4 b2 = *(const float4*)&Ws[k4 * 4 + 2][tx * 4];
        float4 b3 = *(const float4*)&Ws[k4 * 4 + 3][tx * 4];
#pragma unroll
        for (int i = 0; i < 2; i++) {
            float4 a = *(const float4*)&Yc[ty * 2 + i][k4 * 4];
            acc[i][0] += a.x * b0.x + a.y * b1.x + a.z * b2.x + a.w * b3.x;
            acc[i][1] += a.x * b0.y + a.y * b1.y + a.z * b2.y + a.w * b3.y;
            acc[i][2] += a.x * b0.z + a.y * b1.z + a.z * b2.z + a.w * b3.z;
            acc[i][3] += a.x * b0.w + a.y * b1.w + a.z * b2.w + a.w * b3.w;
        }
    }
#pragma unroll
    for (int i = 0; i < 2; i++) {
        size_t r = (size_t)(m0 + ty * 2 + i) * DM + tx * 4;
        *(float4*)&out[r] = make_float4(acc[i][0], acc[i][1], acc[i][2], acc[i][3]);
    }
}

// ---------------- launch ----------------
extern "C" void kernel_launch(void* const* d_in, const int* in_sizes, int n_in,
                              void* d_out, int out_size) {
    const float* x       = (const float*)d_in[0];
    const float* Win     = (const float*)d_in[1];
    const float* conv_w  = (const float*)d_in[2];
    const float* conv_b  = (const float*)d_in[3];
    const float* dt_bias = (const float*)d_in[4];
    const float* A_log   = (const float*)d_in[5];
    const float* Dp      = (const float*)d_in[6];
    const float* norm_w  = (const float*)d_in[7];
    const float* Wout    = (const float*)d_in[8];
    float* outp = (float*)d_out;

    for (int i = 0; i < 8; i++) {
        int insel  = (i == 0) ? -1 : ((i - 1) & 1);
        int outsel = (i == 7) ? -1 : (i & 1);

        k_inproj<<<dim3(6, 512), 128>>>(x, insel, Win + (size_t)i * DM * NPJ,
                                        dt_bias + i * NH, A_log + i * NH);
        k_conv<<<dim3(SL / 32, NB), 192>>>(conv_w + (size_t)i * CDIM * 4,
                                           conv_b + (size_t)i * CDIM);
        k_scanA<<<dim3(NC, NB), 128>>>(Dp + i * NH);
        k_combine<<<NB * NH * 8, 256>>>();
        k_out<<<MROWS / 32, 256>>>(norm_w + (size_t)i * DIN, Wout + (size_t)i * DIN * DM,
                                   outp, outsel);
    }
}

// round 5
// speedup vs baseline: 7.1696x; 1.0226x over previous
#include <cuda_runtime.h>
#include <cstdint>
#include <math.h>

// ---------------- problem constants ----------------
#define NB   16
#define SL   4096
#define DM   64          // d_model
#define DIN  128         // d_inner
#define DST  32          // d_state
#define NH   2           // heads
#define HD   64          // headdim
#define CDIM 192         // d_inner + 2*d_state
#define NPJ  322         // 2*128 + 2*32 + 2
#define MROWS (NB*SL)    // 65536
#define CL   64          // chunk length
#define NC   (SL/CL)     // 64 chunks
#define HSZ  (HD*DST)    // 2048 floats per (b,h,chunk) state

// ---------------- device scratch ----------------
__device__ float  g_z  [(size_t)MROWS * DIN];   // z (gate) only, compact
__device__ float  g_xbc[(size_t)MROWS * CDIM];  // conv+silu activated xBC
__device__ float2 g_dtA[(size_t)MROWS * 2];
__device__ float  g_cd [(size_t)MROWS * 2];     // in-chunk cumulative decay per (row, h)
__device__ float  g_y  [(size_t)MROWS * DIN];
__device__ float  g_buf[2][(size_t)MROWS * DM];
__device__ float  g_hloc[(size_t)NB * NH * NC * HSZ];
__device__ float  g_hin [(size_t)NB * NH * NC * HSZ];

// ---------------- K1: in-proj GEMM (M=65536, N=322, K=64) + fused conv/SiLU + fused dt ----
// 128 threads, block tile 128x64, micro-tile 8x8, A staged transposed.
// Tiles n0=0,64   -> z columns, stored compact to g_z
// Tiles n0=128..256 -> xBC columns: depthwise conv(4)+bias+SiLU fused, stored to g_xbc
// Tile  n0=320    -> dt logits: softplus + exp(dt*A) fused, stored to g_dtA
__global__ __launch_bounds__(128) void k_inproj(const float* __restrict__ xin, int insel,
                                                const float* __restrict__ W,
                                                const float* __restrict__ dt_bias,
                                                const float* __restrict__ A_log,
                                                const float* __restrict__ cw,
                                                const float* __restrict__ cb) {
    __shared__ float pool[12288];                 // 48KB
    float (*Ast)[128] = (float(*)[128])pool;      // [64][128] A transposed
    float (*Bs)[64]   = (float(*)[64])(pool + 8192);
    float (*St)[69]   = (float(*)[69])pool;       // conv staging [131][69] (reuses pool)

    const float* in = (insel >= 0) ? g_buf[insel] : xin;
    const int m0 = blockIdx.y * 128;
    const int n0 = blockIdx.x * 64;
    const int tid = threadIdx.x;

    // A: one row per thread, scattered into transposed layout
    {
        const float4* Arow = (const float4*)(in + (size_t)(m0 + tid) * DM);
#pragma unroll
        for (int q = 0; q < 16; q++) {
            float4 v = Arow[q];
            Ast[q * 4 + 0][tid] = v.x;
            Ast[q * 4 + 1][tid] = v.y;
            Ast[q * 4 + 2][tid] = v.z;
            Ast[q * 4 + 3][tid] = v.w;
        }
    }
    // B tile 64x64 (row stride NPJ), predicated
#pragma unroll
    for (int i = 0; i < 32; i++) {
        int idx = i * 128 + tid;
        int k = idx >> 6, n = idx & 63;
        int gn = n0 + n;
        Bs[k][n] = (gn < NPJ) ? W[k * NPJ + gn] : 0.f;
    }
    __syncthreads();

    const int tx = tid & 7, ty = tid >> 3;   // 8 x 16
    float acc[8][8];
#pragma unroll
    for (int i = 0; i < 8; i++)
#pragma unroll
        for (int j = 0; j < 8; j++) acc[i][j] = 0.f;

#pragma unroll 8
    for (int k = 0; k < 64; k++) {
        float4 a0 = *(const float4*)&Ast[k][ty * 8 + 0];
        float4 a1 = *(const float4*)&Ast[k][ty * 8 + 4];
        float4 b0 = *(const float4*)&Bs[k][tx * 8 + 0];
        float4 b1 = *(const float4*)&Bs[k][tx * 8 + 4];
        float av[8] = {a0.x, a0.y, a0.z, a0.w, a1.x, a1.y, a1.z, a1.w};
        float bv[8] = {b0.x, b0.y, b0.z, b0.w, b1.x, b1.y, b1.z, b1.w};
#pragma unroll
        for (int i = 0; i < 8; i++)
#pragma unroll
            for (int j = 0; j < 8; j++) acc[i][j] += av[i] * bv[j];
    }

    if (n0 < 128) {
        // ---- z tile: compact store ----
#pragma unroll
        for (int i = 0; i < 8; i++) {
            size_t r = (size_t)(m0 + ty * 8 + i) * DIN + n0 + tx * 8;
            *(float4*)&g_z[r + 0] = make_float4(acc[i][0], acc[i][1], acc[i][2], acc[i][3]);
            *(float4*)&g_z[r + 4] = make_float4(acc[i][4], acc[i][5], acc[i][6], acc[i][7]);
        }
    } else if (n0 >= 320) {
        // ---- dt tile ----
        if (tx == 0) {
            const float A0 = -expf(A_log[0]), A1 = -expf(A_log[1]);
            const float b0v = dt_bias[0], b1v = dt_bias[1];
#pragma unroll
            for (int i = 0; i < 8; i++) {
#pragma unroll
                for (int hh = 0; hh < 2; hh++) {
                    float v = acc[i][hh] + (hh ? b1v : b0v);
                    float dt = (v > 15.f) ? v : log1pf(expf(v));
                    float A = hh ? A1 : A0;
                    g_dtA[(size_t)(m0 + ty * 8 + i) * 2 + hh] = make_float2(dt, expf(dt * A));
                }
            }
        }
    } else {
        // ---- xBC tile: fused depthwise conv(4) + bias + SiLU ----
        __syncthreads();   // everyone past mainloop reads of Ast/Bs

        // halo rows (times m0-3..m0-1) for these 64 channels; zero at batch start.
        const bool first = (m0 & (SL - 1)) == 0;
        for (int j = tid; j < 192; j += 128) {
            int r = j >> 6, n = j & 63;
            float s = 0.f;
            if (!first) {
                const float* arow = in + (size_t)(m0 - 3 + r) * DM;
#pragma unroll 16
                for (int k = 0; k < 64; k++) s += arow[k] * Bs[k][n];
            }
            St[r][n] = s;     // rows 0..2 only (does not clash with Bs region)
        }
        __syncthreads();      // halo done reading Bs before acc overwrites pool

        // stage GEMM result at rows 3..130
#pragma unroll
        for (int i = 0; i < 8; i++)
#pragma unroll
            for (int j = 0; j < 8; j++)
                St[3 + ty * 8 + i][tx * 8 + j] = acc[i][j];
        __syncthreads();

        // conv + SiLU + store: thread owns one channel, rows step by 2
        const int c  = tid & 63;
        const int ch = (n0 - 128) + c;
        const float w0 = cw[ch * 4 + 0], w1 = cw[ch * 4 + 1];
        const float w2 = cw[ch * 4 + 2], w3 = cw[ch * 4 + 3];
        const float bb = cb[ch];
        const int rbase = tid >> 6;
        float* outc = g_xbc + (size_t)m0 * CDIM + ch;
#pragma unroll 8
        for (int r = rbase; r < 128; r += 2) {
            float v = bb + w0 * St[r][c] + w1 * St[r + 1][c]
                         + w2 * St[r + 2][c] + w3 * St[r + 3][c];
            v = v / (1.f + expf(-v));
            outc[(size_t)r * CDIM] = v;
        }
    }
}

// ---------------- K3a: single-pass chunk scan from zero state ----------------
__global__ __launch_bounds__(128) void k_scanA(const float* __restrict__ Dp) {
    __shared__ float Bs[CL][DST];
    __shared__ float Cs[CL][DST];
    const int b = blockIdx.y, c = blockIdx.x;
    const int tid = threadIdx.x, h = tid >> 6, p = tid & 63;
    const size_t row0 = (size_t)b * SL + (size_t)c * CL;

#pragma unroll
    for (int i = 0; i < 16; i++) {
        int idx = i * 128 + tid;
        int t = idx >> 5, n = idx & 31;
        const float* src = &g_xbc[(row0 + t) * CDIM + 128];
        Bs[t][n] = src[n];
        Cs[t][n] = src[32 + n];
    }
    __syncthreads();

    const float*  px = g_xbc + row0 * CDIM + h * HD + p;
    const float2* pd = g_dtA + row0 * 2 + h;
    float*        py = g_y + row0 * DIN + h * HD + p;
    float*        pc = g_cd + row0 * 2 + h;
    const float   dp = Dp[h];

    float hs[DST];
#pragma unroll
    for (int n = 0; n < DST; n++) hs[n] = 0.f;
    float cum = 1.f;

#pragma unroll 2
    for (int t = 0; t < CL; t++) {
        float  xv = px[0];
        float2 da = pd[0];
        float  ru = da.x * xv;
        cum *= da.y;
        float a0 = 0.f, a1 = 0.f, a2 = 0.f, a3 = 0.f;
#pragma unroll
        for (int n = 0; n < DST; n += 4) {
            float4 bv = *(const float4*)&Bs[t][n];
            float4 cv = *(const float4*)&Cs[t][n];
            hs[n + 0] = da.y * hs[n + 0] + ru * bv.x;
            hs[n + 1] = da.y * hs[n + 1] + ru * bv.y;
            hs[n + 2] = da.y * hs[n + 2] + ru * bv.z;
            hs[n + 3] = da.y * hs[n + 3] + ru * bv.w;
            a0 += hs[n + 0] * cv.x;
            a1 += hs[n + 1] * cv.y;
            a2 += hs[n + 2] * cv.z;
            a3 += hs[n + 3] * cv.w;
        }
        py[0] = (a0 + a1) + (a2 + a3) + dp * xv;
        if (p == 0) pc[0] = cum;
        px += CDIM; pd += 2; py += DIN; pc += 2;
    }

    float* out = g_hloc + ((((size_t)(b * NH + h) * NC) + c) * HD + p) * DST;
#pragma unroll
    for (int n = 0; n < DST; n += 4)
        *(float4*)&out[n] = make_float4(hs[n], hs[n + 1], hs[n + 2], hs[n + 3]);
}

// ---------------- K3b: combine chunk states (8-deep prefetch pipeline) ----------------
__global__ __launch_bounds__(256) void k_combine() {
    __shared__ float ds[NC];
    const int bh  = blockIdx.x >> 3;
    const int sub = blockIdx.x & 7;
    const int bb  = bh >> 1, hh = bh & 1;
    if (threadIdx.x < NC)
        ds[threadIdx.x] = g_cd[((size_t)bb * SL + threadIdx.x * CL + CL - 1) * 2 + hh];
    __syncthreads();

    const int off = sub * 256 + threadIdx.x;
    const float* loc = g_hloc + (size_t)bh * NC * HSZ + off;
    float*       hin = g_hin  + (size_t)bh * NC * HSZ + off;

    float H = 0.f;
    float buf[8];
#pragma unroll
    for (int j = 0; j < 8; j++) buf[j] = loc[(size_t)j * HSZ];

#pragma unroll
    for (int cb = 0; cb < NC; cb += 8) {
        float nbuf[8];
        if (cb + 8 < NC) {
#pragma unroll
            for (int j = 0; j < 8; j++) nbuf[j] = loc[(size_t)(cb + 8 + j) * HSZ];
        } else {
#pragma unroll
            for (int j = 0; j < 8; j++) nbuf[j] = 0.f;
        }
#pragma unroll
        for (int j = 0; j < 8; j++) {
            hin[(size_t)(cb + j) * HSZ] = H;
            H = ds[cb + j] * H + buf[j];
        }
#pragma unroll
        for (int j = 0; j < 8; j++) buf[j] = nbuf[j];
    }
}

// ---------------- K4: fused correction + gate*silu(z) + RMSNorm + out-proj ----------------
__global__ __launch_bounds__(256) void k_out(const float* __restrict__ nw,
                                             const float* __restrict__ Wout,
                                             float* __restrict__ dout, int outsel) {
    __shared__ float Ws[128][64];    // 32KB
    __shared__ float Yc[32][128];    // 16KB
    __shared__ float Cs[32][32];     // 4KB
    __shared__ float cds[32][2];
    float* out = (outsel >= 0) ? g_buf[outsel] : dout;
    const int m0 = blockIdx.x * 32;
    const int b  = m0 >> 12;
    const int c  = (m0 & (SL - 1)) >> 6;
    const int tid = threadIdx.x;

    {
        float4* Ws4 = (float4*)&Ws[0][0];
        const float4* W4 = (const float4*)Wout;
#pragma unroll
        for (int i = 0; i < 8; i++) Ws4[i * 256 + tid] = W4[i * 256 + tid];
    }
    {
        int t = tid >> 3, n = (tid & 7) * 4;
        *(float4*)&Cs[t][n] = *(const float4*)&g_xbc[(size_t)(m0 + t) * CDIM + 160 + n];
        if (tid < 32) {
            cds[tid][0] = g_cd[(size_t)(m0 + tid) * 2 + 0];
            cds[tid][1] = g_cd[(size_t)(m0 + tid) * 2 + 1];
        }
    }
    __syncthreads();

    // phase A: correction y += cumdecay * (C . H_in)
    {
        const int k = tid & 127, rh = tid >> 7;
        const int h = k >> 6, p = k & 63;
        float Hr[DST];
        const float* hin = g_hin + ((((size_t)(b * NH + h) * NC) + c) * HD + p) * DST;
#pragma unroll
        for (int n = 0; n < DST; n += 4) {
            float4 v = *(const float4*)&hin[n];
            Hr[n] = v.x; Hr[n + 1] = v.y; Hr[n + 2] = v.z; Hr[n + 3] = v.w;
        }
        const float* py = g_y + (size_t)(m0 + rh * 16) * DIN + k;
#pragma unroll 4
        for (int t = 0; t < 16; t++) {
            int row = rh * 16 + t;
            float a0 = 0.f, a1 = 0.f, a2 = 0.f, a3 = 0.f;
#pragma unroll
            for (int n = 0; n < DST; n += 4) {
                float4 cv = *(const float4*)&Cs[row][n];
                a0 += Hr[n + 0] * cv.x;
                a1 += Hr[n + 1] * cv.y;
                a2 += Hr[n + 2] * cv.z;
                a3 += Hr[n + 3] * cv.w;
            }
            Yc[row][k] = py[(size_t)t * DIN] + cds[row][h] * ((a0 + a1) + (a2 + a3));
        }
    }
    __syncthreads();

    // phase B: gate * silu(z), RMSNorm (in-place)
    {
        const int m = tid >> 3, l8 = tid & 7;
        const float* zrow = g_z + (size_t)(m0 + m) * DIN + l8 * 16;
        float4 gv[4];
        float ss = 0.f;
#pragma unroll
        for (int q = 0; q < 4; q++) {
            float4 yv = *(const float4*)&Yc[m][l8 * 16 + q * 4];
            float4 zv = *(const float4*)(zrow + q * 4);
            gv[q].x = yv.x * (zv.x / (1.f + expf(-zv.x)));
            gv[q].y = yv.y * (zv.y / (1.f + expf(-zv.y)));
            gv[q].z = yv.z * (zv.z / (1.f + expf(-zv.z)));
            gv[q].w = yv.w * (zv.w / (1.f + expf(-zv.w)));
            ss += gv[q].x * gv[q].x + gv[q].y * gv[q].y + gv[q].z * gv[q].z + gv[q].w * gv[q].w;
        }
        ss += __shfl_xor_sync(0xffffffffu, ss, 4);
        ss += __shfl_xor_sync(0xffffffffu, ss, 2);
        ss += __shfl_xor_sync(0xffffffffu, ss, 1);
        const float scale = rsqrtf(ss * (1.f / 128.f) + 1e-5f);
#pragma unroll
        for (int q = 0; q < 4; q++) {
            int k = l8 * 16 + q * 4;
            float4 nwv = *(const float4*)(nw + k);
            Yc[m][k + 0] = gv[q].x * scale * nwv.x;
            Yc[m][k + 1] = gv[q].y * scale * nwv.y;
            Yc[m][k + 2] = gv[q].z * scale * nwv.z;
            Yc[m][k + 3] = gv[q].w * scale * nwv.w;
        }
    }
    __syncthreads();

    // phase C: 32x64 GEMM, K=128
    const int tx = tid & 15, ty = tid >> 4;
    float acc[2][4];
#pragma unroll
    for (int i = 0; i < 2; i++)
#pragma unroll
        for (int j = 0; j < 4; j++) acc[i][j] = 0.f;

#pragma unroll
    for (int k4 = 0; k4 < 32; k4++) {
        float4 b0 = *(const float4*)&Ws[k4 * 4 + 0][tx * 4];
        float4 b1 = *(const float4*)&Ws[k4 * 4 + 1][tx * 4];
        float4 b2 = *(const float4*)&Ws[k4 * 4 + 2][tx * 4];
        float4 b3 = *(const float4*)&Ws[k4 * 4 + 3][tx * 4];
#pragma unroll
        for (int i = 0; i < 2; i++) {
            float4 a = *(const float4*)&Yc[ty * 2 + i][k4 * 4];
            acc[i][0] += a.x * b0.x + a.y * b1.x + a.z * b2.x + a.w * b3.x;
            acc[i][1] += a.x * b0.y + a.y * b1.y + a.z * b2.y + a.w * b3.y;
            acc[i][2] += a.x * b0.z + a.y * b1.z + a.z * b2.z + a.w * b3.z;
            acc[i][3] += a.x * b0.w + a.y * b1.w + a.z * b2.w + a.w * b3.w;
        }
    }
#pragma unroll
    for (int i = 0; i < 2; i++) {
        size_t r = (size_t)(m0 + ty * 2 + i) * DM + tx * 4;
        *(float4*)&out[r] = make_float4(acc[i][0], acc[i][1], acc[i][2], acc[i][3]);
    }
}

// ---------------- launch ----------------
extern "C" void kernel_launch(void* const* d_in, const int* in_sizes, int n_in,
                              void* d_out, int out_size) {
    const float* x       = (const float*)d_in[0];
    const float* Win     = (const float*)d_in[1];
    const float* conv_w  = (const float*)d_in[2];
    const float* conv_b  = (const float*)d_in[3];
    const float* dt_bias = (const float*)d_in[4];
    const float* A_log   = (const float*)d_in[5];
    const float* Dp      = (const float*)d_in[6];
    const float* norm_w  = (const float*)d_in[7];
    const float* Wout    = (const float*)d_in[8];
    float* outp = (float*)d_out;

    for (int i = 0; i < 8; i++) {
        int insel  = (i == 0) ? -1 : ((i - 1) & 1);
        int outsel = (i == 7) ? -1 : (i & 1);

        k_inproj<<<dim3(6, 512), 128>>>(x, insel, Win + (size_t)i * DM * NPJ,
                                        dt_bias + i * NH, A_log + i * NH,
                                        conv_w + (size_t)i * CDIM * 4,
                                        conv_b + (size_t)i * CDIM);
        k_scanA<<<dim3(NC, NB), 128>>>(Dp + i * NH);
        k_combine<<<NB * NH * 8, 256>>>();
        k_out<<<MROWS / 32, 256>>>(norm_w + (size_t)i * DIN, Wout + (size_t)i * DIN * DM,
                                   outp, outsel);
    }
}